// round 5
// baseline (speedup 1.0000x reference)
#include <cuda_runtime.h>
#include <cuda_bf16.h>
#include <stdint.h>

#define NN 500000
#define F_IN 165
#define HID 32
#define KX 176          // x K padded to 16
#define KTOT 208        // KX + HID
#define NC 128          // 4 gates * 32
#define BM 64
#define NTILES ((NN + BM - 1) / BM)
#define KCH (KTOT / 16) // 13
#define AST 216         // bf16 row stride (208 + 8 pad) -> ldmatrix conflict-free
#define BST 216
#define CST 132
#define XV4 ((BM * F_IN) / 4)   // 2640 float4 per x tile
#define XIT 11                  // ceil(2640 / 256)

__device__ __nv_bfloat16 g_Bhi[NC * KTOT];
__device__ __nv_bfloat16 g_Blo[NC * KTOT];
__device__ float g_bias[NC];

// Build combined [K=208][N=128] weight matrix (W over x-K, zero pad, Wc over h-K),
// split into bf16 hi/lo, stored as [col][k] for ldmatrix b-frag loads.
__global__ void prep_kernel(
    const float* __restrict__ Wi, const float* __restrict__ Wf,
    const float* __restrict__ Wg, const float* __restrict__ Wo,
    const float* __restrict__ bi, const float* __restrict__ bf2,
    const float* __restrict__ bg, const float* __restrict__ bo,
    const float* __restrict__ Ci, const float* __restrict__ Cf,
    const float* __restrict__ Cg, const float* __restrict__ Co,
    const float* __restrict__ di, const float* __restrict__ df,
    const float* __restrict__ dg, const float* __restrict__ do_)
{
    int idx = blockIdx.x * blockDim.x + threadIdx.x;
    if (idx >= NC * KTOT) return;
    int col = idx & (NC - 1);
    int kk  = idx >> 7;
    int g = col >> 5, j = col & 31;
    const float* W = (g == 0) ? Wi : ((g == 1) ? Wf : ((g == 2) ? Wg : Wo));
    const float* C = (g == 0) ? Ci : ((g == 1) ? Cf : ((g == 2) ? Cg : Co));
    float v = 0.f;
    if (kk < F_IN)      v = W[kk * HID + j];
    else if (kk >= KX)  v = C[(kk - KX) * HID + j];
    __nv_bfloat16 hi = __float2bfloat16(v);
    __nv_bfloat16 lo = __float2bfloat16(v - __bfloat162float(hi));
    g_Bhi[col * KTOT + kk] = hi;
    g_Blo[col * KTOT + kk] = lo;
    if (kk == 0) {
        const float* b = (g == 0) ? bi : ((g == 1) ? bf2 : ((g == 2) ? bg : bo));
        const float* d = (g == 0) ? di : ((g == 1) ? df : ((g == 2) ? dg : do_));
        g_bias[col] = b[j] + d[j];
    }
}

__device__ __forceinline__ void mma_bf16(float c[4], const uint32_t a[4],
                                         uint32_t b0, uint32_t b1) {
    asm volatile(
        "mma.sync.aligned.m16n8k16.row.col.f32.bf16.bf16.f32 "
        "{%0,%1,%2,%3}, {%4,%5,%6,%7}, {%8,%9}, {%0,%1,%2,%3};\n"
        : "+f"(c[0]), "+f"(c[1]), "+f"(c[2]), "+f"(c[3])
        : "r"(a[0]), "r"(a[1]), "r"(a[2]), "r"(a[3]), "r"(b0), "r"(b1));
}

__device__ __forceinline__ void ldsm_x4(uint32_t r[4], uint32_t saddr) {
    asm volatile("ldmatrix.sync.aligned.m8n8.x4.shared.b16 {%0,%1,%2,%3}, [%4];\n"
                 : "=r"(r[0]), "=r"(r[1]), "=r"(r[2]), "=r"(r[3]) : "r"(saddr));
}

// MUFU-based transcendentals: 16 MUFU lane-ops/cyc/SM (rt_SMSP=8) makes these
// ~2.5x cheaper than an all-FMA polynomial path, AND they run on a pipe that
// doesn't compete with the FMA/tensor work. Saturation limits are exact via
// inf propagation (exp->inf -> rcp->0), so no clamps needed.
__device__ __forceinline__ float fsig(float p)  {            // 2 MUFU + 2 FMA
    return __fdividef(1.f, 1.f + __expf(-p));
}
__device__ __forceinline__ float ftanh(float p) {            // 2 MUFU + 3 FMA
    return fmaf(-2.f, __fdividef(1.f, 1.f + __expf(2.f * p)), 1.f);
}

extern "C" __global__ void __launch_bounds__(256, 1)
gclstm_main(const float* __restrict__ x, const float* __restrict__ h,
            const float* __restrict__ cin, const float* __restrict__ Wlin,
            const float* __restrict__ blin, float* __restrict__ out)
{
    extern __shared__ __align__(16) char smem[];
    __nv_bfloat16* Ahi = (__nv_bfloat16*)smem;            // [BM][AST]
    __nv_bfloat16* Alo = Ahi + BM * AST;
    __nv_bfloat16* Bh  = Alo + BM * AST;                  // [NC][BST]
    __nv_bfloat16* Bl  = Bh + NC * BST;
    float* Csh   = (float*)(Bl + NC * BST);               // [BM][CST]
    float* biasS = Csh + BM * CST;                        // [NC]
    float* wlS   = biasS + NC;                            // [64]
    float* blS   = wlS + 64;                              // [2]

    const int tid = threadIdx.x;

    // Pre-zero A buffers once: pad columns (k in [165,176)) stay zero forever.
    for (int i = tid; i < BM * AST / 2; i += 256) {
        ((uint32_t*)Ahi)[i] = 0u;
        ((uint32_t*)Alo)[i] = 0u;
    }
    // Stage full gate-weight matrix (hi/lo) into shared once per CTA.
    for (int i = tid; i < NC * (KTOT / 2); i += 256) {
        int n = i / (KTOT / 2), kw = i - n * (KTOT / 2);
        ((uint32_t*)(Bh + n * BST))[kw] = ((const uint32_t*)(g_Bhi + n * KTOT))[kw];
        ((uint32_t*)(Bl + n * BST))[kw] = ((const uint32_t*)(g_Blo + n * KTOT))[kw];
    }
    if (tid < NC) biasS[tid] = g_bias[tid];
    if (tid < 64) wlS[tid] = Wlin[tid];
    if (tid < 2)  blS[tid] = blin[tid];
    __syncthreads();

    const int warp = tid >> 5, lane = tid & 31;
    const int wm = warp >> 2, wn = warp & 3;     // 2 x 4 warp grid (32x32 tiles)
    const int gq = lane >> 2, t4 = lane & 3;

    const uint32_t smem_u32 = (uint32_t)__cvta_generic_to_shared(smem);
    const int l15 = lane & 15, l16 = lane >> 4;
    const uint32_t aBase0 = smem_u32 +
        (uint32_t)(((wm * 32 + l15) * AST + l16 * 8) * 2);
    const uint32_t dAlo = (uint32_t)(BM * AST * 2);
    const uint32_t bBase0 = smem_u32 + (uint32_t)(2 * BM * AST * 2) +
        (uint32_t)(((wn * 32 + l15) * BST + l16 * 8) * 2);
    const uint32_t dBlo = (uint32_t)(NC * BST * 2);

    float* hout = out + (size_t)NN * 2;
    float* cout = hout + (size_t)NN * HID;
    const size_t xlimit = (size_t)NN * F_IN;

    float4 xbuf[XIT];
    float4 hbuf[2];

    // Prefetch helper (fully inlined; constant trip counts keep bufs in regs).
    auto load_tile = [&](int t) {
        const int r0 = t * BM;
        const size_t xbase = (size_t)r0 * F_IN;   // 16B-aligned (r0 % 64 == 0)
        #pragma unroll
        for (int it = 0; it < XIT; it++) {
            int v = tid + it * 256;
            float4 val = make_float4(0.f, 0.f, 0.f, 0.f);
            if (v < XV4) {
                size_t g0 = xbase + 4 * (size_t)v;
                if (g0 + 3 < xlimit) {
                    val = *(const float4*)(x + g0);
                } else {                       // only the final partial tile
                    if (g0     < xlimit) val.x = x[g0];
                    if (g0 + 1 < xlimit) val.y = x[g0 + 1];
                    if (g0 + 2 < xlimit) val.z = x[g0 + 2];
                    if (g0 + 3 < xlimit) val.w = x[g0 + 3];
                }
            }
            xbuf[it] = val;
        }
        #pragma unroll
        for (int it = 0; it < 2; it++) {
            int v = tid + it * 256;            // < 512 always
            int r = v >> 3;
            float4 val = make_float4(0.f, 0.f, 0.f, 0.f);
            if (r0 + r < NN)
                val = *(const float4*)(h + (size_t)(r0 + r) * HID + (v & 7) * 4);
            hbuf[it] = val;
        }
    };

    int tile = blockIdx.x;
    if (tile < NTILES) load_tile(tile);

    for (; tile < NTILES; tile += gridDim.x) {
        const int row0 = tile * BM;

        // ---- convert prefetched regs -> bf16 hi/lo shared ----
        // (tile-top barrier below also orders prior epilogue's Csh reads
        //  before this tile's C writes -> no end-of-loop barrier needed)
        #pragma unroll
        for (int it = 0; it < XIT; it++) {
            int v = tid + it * 256;
            if (v < XV4) {
                float vv[4] = {xbuf[it].x, xbuf[it].y, xbuf[it].z, xbuf[it].w};
                #pragma unroll
                for (int e = 0; e < 4; e++) {
                    int m = 4 * v + e;
                    int r = m / F_IN;
                    int k = m - r * F_IN;
                    __nv_bfloat16 hi = __float2bfloat16(vv[e]);
                    Ahi[r * AST + k] = hi;
                    Alo[r * AST + k] = __float2bfloat16(vv[e] - __bfloat162float(hi));
                }
            }
        }
        #pragma unroll
        for (int it = 0; it < 2; it++) {
            int v = tid + it * 256;
            int r = v >> 3, k4 = (v & 7) * 4;
            float vv[4] = {hbuf[it].x, hbuf[it].y, hbuf[it].z, hbuf[it].w};
            __nv_bfloat16 hh[4], ll[4];
            #pragma unroll
            for (int e = 0; e < 4; e++) {
                hh[e] = __float2bfloat16(vv[e]);
                ll[e] = __float2bfloat16(vv[e] - __bfloat162float(hh[e]));
            }
            __nv_bfloat16* ph = Ahi + r * AST + KX + k4;
            __nv_bfloat16* pl = Alo + r * AST + KX + k4;
            ((__nv_bfloat162*)ph)[0] = __nv_bfloat162(hh[0], hh[1]);
            ((__nv_bfloat162*)ph)[1] = __nv_bfloat162(hh[2], hh[3]);
            ((__nv_bfloat162*)pl)[0] = __nv_bfloat162(ll[0], ll[1]);
            ((__nv_bfloat162*)pl)[1] = __nv_bfloat162(ll[2], ll[3]);
        }
        __syncthreads();

        // ---- GEMM: 3-term bf16 split, fp32 accumulate, ldmatrix frag loads ----
        float acc[2][4][4];
        #pragma unroll
        for (int mi = 0; mi < 2; mi++)
            #pragma unroll
            for (int ni = 0; ni < 4; ni++)
                #pragma unroll
                for (int q = 0; q < 4; q++) acc[mi][ni][q] = 0.f;

        uint32_t aoff = aBase0, boff = bBase0;
        #pragma unroll
        for (int kc = 0; kc < KCH; kc++) {
            uint32_t ah[2][4], al[2][4], bh[2][4], bl[2][4];
            ldsm_x4(ah[0], aoff);
            ldsm_x4(ah[1], aoff + 16 * AST * 2);
            ldsm_x4(al[0], aoff + dAlo);
            ldsm_x4(al[1], aoff + dAlo + 16 * AST * 2);
            ldsm_x4(bh[0], boff);
            ldsm_x4(bh[1], boff + 16 * BST * 2);
            ldsm_x4(bl[0], boff + dBlo);
            ldsm_x4(bl[1], boff + dBlo + 16 * BST * 2);
            #pragma unroll
            for (int mi = 0; mi < 2; mi++)
                #pragma unroll
                for (int ni = 0; ni < 4; ni++) {
                    const int np = ni >> 1, sl = ni & 1;
                    mma_bf16(acc[mi][ni], ah[mi], bh[np][sl], bh[np][sl + 2]); // hi*hi
                    mma_bf16(acc[mi][ni], ah[mi], bl[np][sl], bl[np][sl + 2]); // hi*lo
                    mma_bf16(acc[mi][ni], al[mi], bh[np][sl], bh[np][sl + 2]); // lo*hi
                }
            aoff += 32; boff += 32;
        }

        // ---- prefetch next tile's DRAM loads: latency hides under epilogue ----
        {
            int nt = tile + gridDim.x;
            if (nt < NTILES) load_tile(nt);
        }

        // ---- preactivations -> shared ----
        #pragma unroll
        for (int mi = 0; mi < 2; mi++)
            #pragma unroll
            for (int ni = 0; ni < 4; ni++) {
                int rr = wm * 32 + mi * 16 + gq;
                int cc = wn * 32 + ni * 8 + 2 * t4;
                *(float2*)&Csh[rr * CST + cc]       = make_float2(acc[mi][ni][0], acc[mi][ni][1]);
                *(float2*)&Csh[(rr + 8) * CST + cc] = make_float2(acc[mi][ni][2], acc[mi][ni][3]);
            }
        __syncthreads();

        // ---- fused LSTM elementwise + classifier epilogue (MUFU fast math) ----
        // thread (rloc = tid>>2, part = tid&3) handles j = part + 4*jj:
        // Csh read bank = (4*rloc + part) mod 32 = tid mod 32 -> conflict-free
        {
            const int rloc = tid >> 2;
            const int part = tid & 3;
            const int grow = row0 + rloc;
            const bool valid = grow < NN;

            float cold[8];
            #pragma unroll
            for (int jj = 0; jj < 8; jj++)       // batched independent LDGs (MLP=8)
                cold[jj] = valid ? __ldg(&cin[grow * HID + part + 4 * jj]) : 0.f;

            float y0 = 0.f, y1 = 0.f;
            float h0v[8], c0v[8];
            #pragma unroll
            for (int jj = 0; jj < 8; jj++) {
                int j = part + 4 * jj;
                float pi = Csh[rloc * CST + j]      + biasS[j];
                float pf = Csh[rloc * CST + 32 + j] + biasS[32 + j];
                float pg = Csh[rloc * CST + 64 + j] + biasS[64 + j];
                float po = Csh[rloc * CST + 96 + j] + biasS[96 + j];
                float iv = fsig(pi);
                float fv = fsig(pf);
                float gv = ftanh(pg);
                float ov = fsig(po);
                float c0 = fv * cold[jj] + iv * gv;
                float h0 = ov * ftanh(c0);
                c0v[jj] = c0; h0v[jj] = h0;
                float r = h0 > 0.f ? h0 : 0.f;
                y0 += r * wlS[2 * j];
                y1 += r * wlS[2 * j + 1];
            }
            y0 += __shfl_down_sync(0xffffffffu, y0, 2, 4);
            y0 += __shfl_down_sync(0xffffffffu, y0, 1, 4);
            y1 += __shfl_down_sync(0xffffffffu, y1, 2, 4);
            y1 += __shfl_down_sync(0xffffffffu, y1, 1, 4);

            if (valid) {
                #pragma unroll
                for (int jj = 0; jj < 8; jj++) {
                    int j = part + 4 * jj;
                    hout[grow * HID + j] = h0v[jj];
                    cout[grow * HID + j] = c0v[jj];
                }
                if (part == 0) {
                    *(float2*)&out[(size_t)grow * 2] = make_float2(y0 + blS[0], y1 + blS[1]);
                }
            }
        }
        // no end-of-loop barrier: next tile-top __syncthreads orders everything
    }
}

extern "C" void kernel_launch(void* const* d_in, const int* in_sizes, int n_in,
                              void* d_out, int out_size)
{
    (void)in_sizes; (void)n_in; (void)out_size;
    const float* x    = (const float*)d_in[0];
    // d_in[1] edge_index (int64), d_in[2] edge_weight: unused (ChebConv K=1)
    const float* h    = (const float*)d_in[3];
    const float* c    = (const float*)d_in[4];
    const float* Wi   = (const float*)d_in[5];
    const float* Wf   = (const float*)d_in[6];
    const float* Wg   = (const float*)d_in[7];
    const float* Wo   = (const float*)d_in[8];
    const float* bi   = (const float*)d_in[9];
    const float* bf2  = (const float*)d_in[10];
    const float* bg   = (const float*)d_in[11];
    const float* bo   = (const float*)d_in[12];
    const float* Ci   = (const float*)d_in[13];
    const float* Cf   = (const float*)d_in[14];
    const float* Cg   = (const float*)d_in[15];
    const float* Co   = (const float*)d_in[16];
    const float* di   = (const float*)d_in[17];
    const float* df   = (const float*)d_in[18];
    const float* dg   = (const float*)d_in[19];
    const float* do_  = (const float*)d_in[20];
    const float* Wlin = (const float*)d_in[21];
    const float* blin = (const float*)d_in[22];

    prep_kernel<<<(NC * KTOT + 255) / 256, 256>>>(Wi, Wf, Wg, Wo, bi, bf2, bg, bo,
                                                  Ci, Cf, Cg, Co, di, df, dg, do_);

    int smem_bytes = (2 * BM * AST + 2 * NC * BST) * 2          // bf16 A + B (hi/lo)
                   + (BM * CST + NC + 64 + 2) * 4;              // fp32 C + bias + Wlin + blin
    cudaFuncSetAttribute(gclstm_main, cudaFuncAttributeMaxDynamicSharedMemorySize, smem_bytes);

    int nsm = 148;
    cudaDeviceGetAttribute(&nsm, cudaDevAttrMultiProcessorCount, 0);

    gclstm_main<<<nsm, 256, smem_bytes>>>(x, h, c, Wlin, blin, (float*)d_out);
}